// round 6
// baseline (speedup 1.0000x reference)
#include <cuda_runtime.h>

#define N_USERS 50000
#define N_ENT   150000
#define N_NODES 200000
#define NE      2000000
#define BATCH   8192
#define NBLK    ((N_NODES + 255) / 256)   // 782

// ---------------- static device scratch (no allocations allowed) ----------------
__device__ float g_ego [(size_t)N_NODES * 64];   // current ego embeddings (row stride 64)
__device__ float g_side[(size_t)N_NODES * 64];   // SpMM result        (row stride 64)
__device__ float g_emb1[(size_t)N_NODES * 64];   // l2-normed layer-1 output
__device__ float g_emb2[(size_t)N_NODES * 32];   // l2-normed layer-2 output
__device__ float g_emb3[(size_t)N_NODES * 16];   // l2-normed layer-3 output
__device__ int   g_rowptr[N_NODES + 1];
__device__ int   g_cursor[N_NODES];              // doubles as histogram counts
__device__ int   g_colsort[NE];
__device__ float g_valsort[NE];
__device__ int   g_blksums[1024];
__device__ int   g_blkoff [1024];

__device__ __forceinline__ float lrelu(float v) { return v > 0.f ? v : 0.01f * v; }

// ---------------- init: ego = concat(user_embed, entity_embed) ----------------
__global__ void k_init_ego(const float* __restrict__ ue, const float* __restrict__ ee) {
    int i = blockIdx.x * blockDim.x + threadIdx.x;     // float4 index
    const int total = N_NODES * 16;                    // N*64/4
    if (i >= total) return;
    const int uf4 = N_USERS * 16;
    float4 v = (i < uf4) ? ((const float4*)ue)[i] : ((const float4*)ee)[i - uf4];
    ((float4*)g_ego)[i] = v;
}

// ---------------- CSR build ----------------
__global__ void k_zero_cnt() {
    int i = blockIdx.x * 256 + threadIdx.x;
    if (i < N_NODES) g_cursor[i] = 0;
}

__global__ void k_hist(const int* __restrict__ rows) {
    int e = blockIdx.x * 256 + threadIdx.x;
    if (e < NE) atomicAdd(&g_cursor[rows[e]], 1);
}

__global__ void k_scan_local() {
    int tid = threadIdx.x;
    int i = blockIdx.x * 256 + tid;
    int v = (i < N_NODES) ? g_cursor[i] : 0;
    int lane = tid & 31, w = tid >> 5;
    int inc = v;
#pragma unroll
    for (int o = 1; o < 32; o <<= 1) {
        int t = __shfl_up_sync(0xffffffffu, inc, o);
        if (lane >= o) inc += t;
    }
    __shared__ int ws[8];
    if (lane == 31) ws[w] = inc;
    __syncthreads();
    if (tid < 8) {
        int s = ws[tid];
#pragma unroll
        for (int o = 1; o < 8; o <<= 1) {
            int t = __shfl_up_sync(0xffu, s, o);
            if (tid >= o) s += t;
        }
        ws[tid] = s;
    }
    __syncthreads();
    int base = (w > 0) ? ws[w - 1] : 0;
    if (i < N_NODES) g_rowptr[i] = base + inc - v;     // exclusive scan
    if (tid == 0) g_blksums[blockIdx.x] = ws[7];       // block total
}

__global__ void k_scan_blk() {
    __shared__ int sm[1024];
    int tid = threadIdx.x;
    int v = (tid < NBLK) ? g_blksums[tid] : 0;
    sm[tid] = v;
    __syncthreads();
    for (int o = 1; o < 1024; o <<= 1) {
        int t = (tid >= o) ? sm[tid - o] : 0;
        __syncthreads();
        sm[tid] += t;
        __syncthreads();
    }
    if (tid < NBLK) g_blkoff[tid] = sm[tid] - v;       // exclusive
}

__global__ void k_addoff() {
    int i = blockIdx.x * 256 + threadIdx.x;
    if (i < N_NODES) {
        int v = g_rowptr[i] + g_blkoff[i >> 8];
        g_rowptr[i] = v;
        g_cursor[i] = v;
    }
    if (i == 0) g_rowptr[N_NODES] = NE;
}

__global__ void k_scatter(const int* __restrict__ rows, const int* __restrict__ cols,
                          const float* __restrict__ ev) {
    int e = blockIdx.x * 256 + threadIdx.x;
    if (e < NE) {
        int r = rows[e];
        int p = atomicAdd(&g_cursor[r], 1);
        g_colsort[p] = cols[e];
        g_valsort[p] = ev[e];
    }
}

// ---------------- SpMM: side[r,:] = sum_e val[e] * ego[col[e],:]  (warp per row) ----------------
template <int D>
__global__ void k_spmm() {
    int gw = (blockIdx.x * blockDim.x + threadIdx.x) >> 5;
    int lane = threadIdx.x & 31;
    if (gw >= N_NODES) return;
    int s = g_rowptr[gw], t = g_rowptr[gw + 1];
    if (D == 64) {
        float2 acc = make_float2(0.f, 0.f);
        const float2* eg = (const float2*)g_ego;
        for (int e = s; e < t; e++) {
            int c = __ldg(&g_colsort[e]);
            float v = __ldg(&g_valsort[e]);
            float2 x = eg[(size_t)c * 32 + lane];
            acc.x += v * x.x;
            acc.y += v * x.y;
        }
        ((float2*)g_side)[(size_t)gw * 32 + lane] = acc;
    } else {  // D == 32
        float acc = 0.f;
        for (int e = s; e < t; e++) {
            int c = __ldg(&g_colsort[e]);
            float v = __ldg(&g_valsort[e]);
            acc += v * g_ego[(size_t)c * 64 + lane];
        }
        g_side[(size_t)gw * 64 + lane] = acc;
    }
}

// ---------------- dense layer: ego = lrelu((ego+side)Wg+bg) + lrelu((ego*side)Wb+bb); emb = l2norm(ego) ----------------
template <int DIN, int DOUT, int L>
__global__ __launch_bounds__(128) void k_dense(const float* __restrict__ Wg, const float* __restrict__ bg,
                                               const float* __restrict__ Wb, const float* __restrict__ bb) {
    __shared__ __align__(16) float sWg[DIN * DOUT];
    __shared__ __align__(16) float sWb[DIN * DOUT];
    __shared__ float sbg[DOUT], sbb[DOUT];
    int tid = threadIdx.x;
    for (int i = tid; i < DIN * DOUT; i += 128) { sWg[i] = Wg[i]; sWb[i] = Wb[i]; }
    if (tid < DOUT) { sbg[tid] = bg[tid]; sbb[tid] = bb[tid]; }
    __syncthreads();

    int r = blockIdx.x * 128 + tid;
    if (r >= N_NODES) return;

    float x[DIN], p[DIN];
    const float4* er = (const float4*)(g_ego  + (size_t)r * 64);
    const float4* sr = (const float4*)(g_side + (size_t)r * 64);
#pragma unroll
    for (int k = 0; k < DIN / 4; k++) {
        float4 a = er[k], b = sr[k];
        x[4 * k + 0] = a.x + b.x;  p[4 * k + 0] = a.x * b.x;
        x[4 * k + 1] = a.y + b.y;  p[4 * k + 1] = a.y * b.y;
        x[4 * k + 2] = a.z + b.z;  p[4 * k + 2] = a.z * b.z;
        x[4 * k + 3] = a.w + b.w;  p[4 * k + 3] = a.w * b.w;
    }

    float* orow = g_ego + (size_t)r * 64;
    float nrm = 0.f;
#pragma unroll 1
    for (int j0 = 0; j0 < DOUT; j0 += 4) {
        float g0 = sbg[j0], g1 = sbg[j0 + 1], g2 = sbg[j0 + 2], g3 = sbg[j0 + 3];
        float c0 = sbb[j0], c1 = sbb[j0 + 1], c2 = sbb[j0 + 2], c3 = sbb[j0 + 3];
#pragma unroll
        for (int k = 0; k < DIN; k++) {
            float xk = x[k], pk = p[k];
            float4 wg = *(const float4*)&sWg[k * DOUT + j0];
            float4 wb = *(const float4*)&sWb[k * DOUT + j0];
            g0 += xk * wg.x;  g1 += xk * wg.y;  g2 += xk * wg.z;  g3 += xk * wg.w;
            c0 += pk * wb.x;  c1 += pk * wb.y;  c2 += pk * wb.z;  c3 += pk * wb.w;
        }
        float o0 = lrelu(g0) + lrelu(c0);
        float o1 = lrelu(g1) + lrelu(c1);
        float o2 = lrelu(g2) + lrelu(c2);
        float o3 = lrelu(g3) + lrelu(c3);
        orow[j0 + 0] = o0;  orow[j0 + 1] = o1;  orow[j0 + 2] = o2;  orow[j0 + 3] = o3;
        nrm += o0 * o0 + o1 * o1 + o2 * o2 + o3 * o3;
    }

    float inv = 1.f / fmaxf(sqrtf(nrm), 1e-12f);
    float* em = (L == 1) ? (g_emb1 + (size_t)r * 64)
              : (L == 2) ? (g_emb2 + (size_t)r * 32)
                         : (g_emb3 + (size_t)r * 16);
#pragma unroll
    for (int j = 0; j < DOUT; j++) em[j] = orow[j] * inv;
}

// ---------------- scoring: warp per sample, 176-dim dots ----------------
__global__ void k_score(const int* __restrict__ users, const int* __restrict__ pos,
                        const int* __restrict__ neg,
                        const float* __restrict__ ue, const float* __restrict__ ee,
                        float* __restrict__ out) {
    int gw = (blockIdx.x * blockDim.x + threadIdx.x) >> 5;
    int lane = threadIdx.x & 31;
    if (gw >= BATCH) return;
    int u  = users[gw];
    int pi = pos[gw];
    int ni = neg[gw];
    int pr = N_USERS + pi;   // rows in full-node emb buffers
    int nr = N_USERS + ni;

    float ps = 0.f, ns = 0.f;
    // segment 0: initial embeddings (64) — read directly from inputs
#pragma unroll
    for (int i = 0; i < 2; i++) {
        int d = lane + 32 * i;
        float uv = ue[(size_t)u * 64 + d];
        ps += uv * ee[(size_t)pi * 64 + d];
        ns += uv * ee[(size_t)ni * 64 + d];
    }
    // segment 1: layer-1 normed (64)
#pragma unroll
    for (int i = 0; i < 2; i++) {
        int d = lane + 32 * i;
        float uv = g_emb1[(size_t)u * 64 + d];
        ps += uv * g_emb1[(size_t)pr * 64 + d];
        ns += uv * g_emb1[(size_t)nr * 64 + d];
    }
    // segment 2: layer-2 normed (32)
    {
        float uv = g_emb2[(size_t)u * 32 + lane];
        ps += uv * g_emb2[(size_t)pr * 32 + lane];
        ns += uv * g_emb2[(size_t)nr * 32 + lane];
    }
    // segment 3: layer-3 normed (16)
    if (lane < 16) {
        float uv = g_emb3[(size_t)u * 16 + lane];
        ps += uv * g_emb3[(size_t)pr * 16 + lane];
        ns += uv * g_emb3[(size_t)nr * 16 + lane];
    }
#pragma unroll
    for (int o = 16; o > 0; o >>= 1) {
        ps += __shfl_xor_sync(0xffffffffu, ps, o);
        ns += __shfl_xor_sync(0xffffffffu, ns, o);
    }
    if (lane == 0) {
        out[(size_t)gw * 2 + 0] = ps;
        out[(size_t)gw * 2 + 1] = ns;
    }
}

// ---------------- launch ----------------
extern "C" void kernel_launch(void* const* d_in, const int* in_sizes, int n_in,
                              void* d_out, int out_size) {
    const int*   users = (const int*)d_in[0];
    const int*   pos   = (const int*)d_in[1];
    const int*   neg   = (const int*)d_in[2];
    const int*   rows  = (const int*)d_in[3];
    const int*   cols  = (const int*)d_in[4];
    const float* ev    = (const float*)d_in[5];
    const float* ue    = (const float*)d_in[6];
    const float* ee    = (const float*)d_in[7];
    const float* Wg0 = (const float*)d_in[8],  *bg0 = (const float*)d_in[9];
    const float* Wb0 = (const float*)d_in[10], *bb0 = (const float*)d_in[11];
    const float* Wg1 = (const float*)d_in[12], *bg1 = (const float*)d_in[13];
    const float* Wb1 = (const float*)d_in[14], *bb1 = (const float*)d_in[15];
    const float* Wg2 = (const float*)d_in[16], *bg2 = (const float*)d_in[17];
    const float* Wb2 = (const float*)d_in[18], *bb2 = (const float*)d_in[19];
    float* out = (float*)d_out;

    // ego init + CSR build (CSR reused by all 3 layers)
    k_init_ego<<<(N_NODES * 16 + 255) / 256, 256>>>(ue, ee);
    k_zero_cnt<<<NBLK, 256>>>();
    k_hist<<<(NE + 255) / 256, 256>>>(rows);
    k_scan_local<<<NBLK, 256>>>();
    k_scan_blk<<<1, 1024>>>();
    k_addoff<<<NBLK, 256>>>();
    k_scatter<<<(NE + 255) / 256, 256>>>(rows, cols, ev);

    const int spmm_blocks = (N_NODES * 32 + 255) / 256;
    const int dense_blocks = (N_NODES + 127) / 128;

    // layer 0: 64 -> 64
    k_spmm<64><<<spmm_blocks, 256>>>();
    k_dense<64, 64, 1><<<dense_blocks, 128>>>(Wg0, bg0, Wb0, bb0);
    // layer 1: 64 -> 32
    k_spmm<64><<<spmm_blocks, 256>>>();
    k_dense<64, 32, 2><<<dense_blocks, 128>>>(Wg1, bg1, Wb1, bb1);
    // layer 2: 32 -> 16
    k_spmm<32><<<spmm_blocks, 256>>>();
    k_dense<32, 16, 3><<<dense_blocks, 128>>>(Wg2, bg2, Wb2, bb2);

    // scoring
    k_score<<<(BATCH * 32 + 255) / 256, 256>>>(users, pos, neg, ue, ee, out);
    (void)in_sizes; (void)n_in; (void)out_size;
}

// round 7
// speedup vs baseline: 1.1439x; 1.1439x over previous
#include <cuda_runtime.h>

#define N_USERS 50000
#define N_ENT   150000
#define N_NODES 200000
#define NE      2000000
#define BATCH   8192
#define NBLK    ((N_NODES + 255) / 256)   // 782

// ---------------- static device scratch (no allocations allowed) ----------------
__device__ float g_ego [(size_t)N_NODES * 64];   // current ego embeddings (row stride 64)
__device__ float g_side[(size_t)N_NODES * 64];   // SpMM result        (row stride 64)
__device__ float g_emb1[(size_t)N_NODES * 64];   // l2-normed layer-1 output
__device__ float g_emb2[(size_t)N_NODES * 32];   // l2-normed layer-2 output
__device__ float g_emb3[(size_t)N_NODES * 16];   // l2-normed layer-3 output
__device__ int   g_rowptr[N_NODES + 1];
__device__ int   g_cursor[N_NODES];              // doubles as histogram counts
__device__ int2  g_edge[NE];                     // packed (col, val_bits), CSR order
__device__ int   g_blksums[1024];
__device__ int   g_blkoff [1024];

__device__ __forceinline__ float lrelu(float v) { return v > 0.f ? v : 0.01f * v; }

// -------- f32x2 packed helpers (FFMA2 path — ptxas never auto-fuses this) --------
__device__ __forceinline__ unsigned long long pk2(float a, float b) {
    unsigned long long r;
    asm("mov.b64 %0, {%1, %2};" : "=l"(r) : "f"(a), "f"(b));
    return r;
}
__device__ __forceinline__ void upk2(unsigned long long v, float& a, float& b) {
    asm("mov.b64 {%0, %1}, %2;" : "=f"(a), "=f"(b) : "l"(v));
}
__device__ __forceinline__ unsigned long long ffma2(unsigned long long a, unsigned long long b,
                                                    unsigned long long c) {
    unsigned long long d;
    asm("fma.rn.f32x2 %0, %1, %2, %3;" : "=l"(d) : "l"(a), "l"(b), "l"(c));
    return d;
}

// ---------------- init: ego = concat(user_embed, entity_embed) ----------------
__global__ void k_init_ego(const float* __restrict__ ue, const float* __restrict__ ee) {
    int i = blockIdx.x * blockDim.x + threadIdx.x;     // float4 index
    const int total = N_NODES * 16;                    // N*64/4
    if (i >= total) return;
    const int uf4 = N_USERS * 16;
    float4 v = (i < uf4) ? ((const float4*)ue)[i] : ((const float4*)ee)[i - uf4];
    ((float4*)g_ego)[i] = v;
}

// ---------------- CSR build ----------------
__global__ void k_zero_cnt() {
    int i = blockIdx.x * 256 + threadIdx.x;
    if (i < N_NODES) g_cursor[i] = 0;
}

__global__ void k_hist(const int* __restrict__ rows) {
    int e = blockIdx.x * 256 + threadIdx.x;
    if (e < NE) atomicAdd(&g_cursor[rows[e]], 1);
}

__global__ void k_scan_local() {
    int tid = threadIdx.x;
    int i = blockIdx.x * 256 + tid;
    int v = (i < N_NODES) ? g_cursor[i] : 0;
    int lane = tid & 31, w = tid >> 5;
    int inc = v;
#pragma unroll
    for (int o = 1; o < 32; o <<= 1) {
        int t = __shfl_up_sync(0xffffffffu, inc, o);
        if (lane >= o) inc += t;
    }
    __shared__ int ws[8];
    if (lane == 31) ws[w] = inc;
    __syncthreads();
    if (tid < 8) {
        int s = ws[tid];
#pragma unroll
        for (int o = 1; o < 8; o <<= 1) {
            int t = __shfl_up_sync(0xffu, s, o);
            if (tid >= o) s += t;
        }
        ws[tid] = s;
    }
    __syncthreads();
    int base = (w > 0) ? ws[w - 1] : 0;
    if (i < N_NODES) g_rowptr[i] = base + inc - v;     // exclusive scan
    if (tid == 0) g_blksums[blockIdx.x] = ws[7];       // block total
}

__global__ void k_scan_blk() {
    __shared__ int sm[1024];
    int tid = threadIdx.x;
    int v = (tid < NBLK) ? g_blksums[tid] : 0;
    sm[tid] = v;
    __syncthreads();
    for (int o = 1; o < 1024; o <<= 1) {
        int t = (tid >= o) ? sm[tid - o] : 0;
        __syncthreads();
        sm[tid] += t;
        __syncthreads();
    }
    if (tid < NBLK) g_blkoff[tid] = sm[tid] - v;       // exclusive
}

__global__ void k_addoff() {
    int i = blockIdx.x * 256 + threadIdx.x;
    if (i < N_NODES) {
        int v = g_rowptr[i] + g_blkoff[i >> 8];
        g_rowptr[i] = v;
        g_cursor[i] = v;
    }
    if (i == 0) g_rowptr[N_NODES] = NE;
}

__global__ void k_scatter(const int* __restrict__ rows, const int* __restrict__ cols,
                          const float* __restrict__ ev) {
    int e = blockIdx.x * 256 + threadIdx.x;
    if (e < NE) {
        int r = rows[e];
        int p = atomicAdd(&g_cursor[r], 1);
        g_edge[p] = make_int2(cols[e], __float_as_int(ev[e]));
    }
}

// ---------------- SpMM: side[r,:] = sum_e val[e] * ego[col[e],:] ----------------
// LPR lanes per row, each lane holds one float4 of the row (LPR*4 = dim).
// Edge stream software-pipelined one iteration ahead so the dependent gather
// overlaps the next index load.
template <int LPR>
__global__ void k_spmm() {
    int gt = blockIdx.x * blockDim.x + threadIdx.x;
    int row = gt / LPR;
    int lane = threadIdx.x & (LPR - 1);
    if (row >= N_NODES) return;
    int s = g_rowptr[row], t = g_rowptr[row + 1];
    const float4* eg = (const float4*)g_ego;     // ego row stride = 16 float4
    float4 acc = make_float4(0.f, 0.f, 0.f, 0.f);
    int2 nxt = make_int2(0, 0);
    if (s < t) nxt = __ldg(&g_edge[s]);
    for (int e = s; e < t; e++) {
        int2 cur = nxt;
        if (e + 1 < t) nxt = __ldg(&g_edge[e + 1]);
        float v = __int_as_float(cur.y);
        float4 x = eg[(size_t)cur.x * 16 + lane];
        acc.x += v * x.x;  acc.y += v * x.y;
        acc.z += v * x.z;  acc.w += v * x.w;
    }
    ((float4*)g_side)[(size_t)row * 16 + lane] = acc;
}

// ---------------- dense layer (f32x2 packed accumulators, k-outer) ----------------
// ego = lrelu((ego+side)Wg+bg) + lrelu((ego*side)Wb+bb); emb = l2norm(ego)
template <int DIN, int DOUT, int L>
__global__ __launch_bounds__(128) void k_dense(const float* __restrict__ Wg, const float* __restrict__ bg,
                                               const float* __restrict__ Wb, const float* __restrict__ bb) {
    __shared__ __align__(16) float sWg[DIN * DOUT];
    __shared__ __align__(16) float sWb[DIN * DOUT];
    __shared__ float sb[2 * DOUT];
    int tid = threadIdx.x;
    for (int i = tid; i < DIN * DOUT; i += 128) { sWg[i] = Wg[i]; sWb[i] = Wb[i]; }
    if (tid < DOUT) { sb[tid] = bg[tid]; sb[DOUT + tid] = bb[tid]; }
    __syncthreads();

    int r = blockIdx.x * 128 + tid;
    if (r >= N_NODES) return;

    constexpr int NJ = DOUT / 2;   // u64 accumulators (pairs of outputs)
    unsigned long long ag[NJ], ac[NJ];
#pragma unroll
    for (int j = 0; j < NJ; j++) {
        ag[j] = pk2(sb[2 * j], sb[2 * j + 1]);
        ac[j] = pk2(sb[DOUT + 2 * j], sb[DOUT + 2 * j + 1]);
    }

    const float4* er = (const float4*)(g_ego  + (size_t)r * 64);
    const float4* sr = (const float4*)(g_side + (size_t)r * 64);

#pragma unroll 1
    for (int k4 = 0; k4 < DIN / 4; k4++) {
        float4 a = er[k4], b = sr[k4];
        float xs0 = a.x + b.x, xs1 = a.y + b.y, xs2 = a.z + b.z, xs3 = a.w + b.w;
        float ps0 = a.x * b.x, ps1 = a.y * b.y, ps2 = a.z * b.z, ps3 = a.w * b.w;
#pragma unroll
        for (int t = 0; t < 4; t++) {
            float xv = (t == 0) ? xs0 : (t == 1) ? xs1 : (t == 2) ? xs2 : xs3;
            float pv = (t == 0) ? ps0 : (t == 1) ? ps1 : (t == 2) ? ps2 : ps3;
            int k = 4 * k4 + t;
            unsigned long long x2 = pk2(xv, xv);
            unsigned long long p2 = pk2(pv, pv);
            const ulonglong2* wg = (const ulonglong2*)&sWg[k * DOUT];
            const ulonglong2* wb = (const ulonglong2*)&sWb[k * DOUT];
#pragma unroll
            for (int j2 = 0; j2 < NJ / 2; j2++) {
                ulonglong2 w1 = wg[j2];
                ag[2 * j2 + 0] = ffma2(x2, w1.x, ag[2 * j2 + 0]);
                ag[2 * j2 + 1] = ffma2(x2, w1.y, ag[2 * j2 + 1]);
                ulonglong2 w2 = wb[j2];
                ac[2 * j2 + 0] = ffma2(p2, w2.x, ac[2 * j2 + 0]);
                ac[2 * j2 + 1] = ffma2(p2, w2.y, ac[2 * j2 + 1]);
            }
        }
    }

    // epilogue: lrelu-combine, write ego in place, keep packed for norm pass
    float* orow = g_ego + (size_t)r * 64;
    float nrm = 0.f;
#pragma unroll
    for (int j = 0; j < NJ; j++) {
        float g0, g1, c0, c1;
        upk2(ag[j], g0, g1);
        upk2(ac[j], c0, c1);
        float o0 = lrelu(g0) + lrelu(c0);
        float o1 = lrelu(g1) + lrelu(c1);
        orow[2 * j] = o0;  orow[2 * j + 1] = o1;
        nrm += o0 * o0 + o1 * o1;
        ag[j] = pk2(o0, o1);        // reuse accumulator storage for normalize pass
    }
    float inv = 1.f / fmaxf(sqrtf(nrm), 1e-12f);
    float* em = (L == 1) ? (g_emb1 + (size_t)r * 64)
              : (L == 2) ? (g_emb2 + (size_t)r * 32)
                         : (g_emb3 + (size_t)r * 16);
#pragma unroll
    for (int j = 0; j < NJ; j++) {
        float o0, o1;
        upk2(ag[j], o0, o1);
        em[2 * j] = o0 * inv;  em[2 * j + 1] = o1 * inv;
    }
}

// ---------------- scoring: warp per sample, 176-dim dots ----------------
__global__ void k_score(const int* __restrict__ users, const int* __restrict__ pos,
                        const int* __restrict__ neg,
                        const float* __restrict__ ue, const float* __restrict__ ee,
                        float* __restrict__ out) {
    int gw = (blockIdx.x * blockDim.x + threadIdx.x) >> 5;
    int lane = threadIdx.x & 31;
    if (gw >= BATCH) return;
    int u  = users[gw];
    int pi = pos[gw];
    int ni = neg[gw];
    int pr = N_USERS + pi;   // rows in full-node emb buffers
    int nr = N_USERS + ni;

    float ps = 0.f, ns = 0.f;
#pragma unroll
    for (int i = 0; i < 2; i++) {
        int d = lane + 32 * i;
        float uv = ue[(size_t)u * 64 + d];
        ps += uv * ee[(size_t)pi * 64 + d];
        ns += uv * ee[(size_t)ni * 64 + d];
    }
#pragma unroll
    for (int i = 0; i < 2; i++) {
        int d = lane + 32 * i;
        float uv = g_emb1[(size_t)u * 64 + d];
        ps += uv * g_emb1[(size_t)pr * 64 + d];
        ns += uv * g_emb1[(size_t)nr * 64 + d];
    }
    {
        float uv = g_emb2[(size_t)u * 32 + lane];
        ps += uv * g_emb2[(size_t)pr * 32 + lane];
        ns += uv * g_emb2[(size_t)nr * 32 + lane];
    }
    if (lane < 16) {
        float uv = g_emb3[(size_t)u * 16 + lane];
        ps += uv * g_emb3[(size_t)pr * 16 + lane];
        ns += uv * g_emb3[(size_t)nr * 16 + lane];
    }
#pragma unroll
    for (int o = 16; o > 0; o >>= 1) {
        ps += __shfl_xor_sync(0xffffffffu, ps, o);
        ns += __shfl_xor_sync(0xffffffffu, ns, o);
    }
    if (lane == 0) {
        out[(size_t)gw * 2 + 0] = ps;
        out[(size_t)gw * 2 + 1] = ns;
    }
}

// ---------------- launch ----------------
extern "C" void kernel_launch(void* const* d_in, const int* in_sizes, int n_in,
                              void* d_out, int out_size) {
    const int*   users = (const int*)d_in[0];
    const int*   pos   = (const int*)d_in[1];
    const int*   neg   = (const int*)d_in[2];
    const int*   rows  = (const int*)d_in[3];
    const int*   cols  = (const int*)d_in[4];
    const float* ev    = (const float*)d_in[5];
    const float* ue    = (const float*)d_in[6];
    const float* ee    = (const float*)d_in[7];
    const float* Wg0 = (const float*)d_in[8],  *bg0 = (const float*)d_in[9];
    const float* Wb0 = (const float*)d_in[10], *bb0 = (const float*)d_in[11];
    const float* Wg1 = (const float*)d_in[12], *bg1 = (const float*)d_in[13];
    const float* Wb1 = (const float*)d_in[14], *bb1 = (const float*)d_in[15];
    const float* Wg2 = (const float*)d_in[16], *bg2 = (const float*)d_in[17];
    const float* Wb2 = (const float*)d_in[18], *bb2 = (const float*)d_in[19];
    float* out = (float*)d_out;

    // ego init + CSR build (CSR reused by all 3 layers)
    k_init_ego<<<(N_NODES * 16 + 255) / 256, 256>>>(ue, ee);
    k_zero_cnt<<<NBLK, 256>>>();
    k_hist<<<(NE + 255) / 256, 256>>>(rows);
    k_scan_local<<<NBLK, 256>>>();
    k_scan_blk<<<1, 1024>>>();
    k_addoff<<<NBLK, 256>>>();
    k_scatter<<<(NE + 255) / 256, 256>>>(rows, cols, ev);

    const int dense_blocks = (N_NODES + 127) / 128;
    const int spmm16_blocks = (N_NODES * 16 + 255) / 256;
    const int spmm8_blocks  = (N_NODES * 8 + 255) / 256;

    // layer 0: 64 -> 64
    k_spmm<16><<<spmm16_blocks, 256>>>();
    k_dense<64, 64, 1><<<dense_blocks, 128>>>(Wg0, bg0, Wb0, bb0);
    // layer 1: 64 -> 32
    k_spmm<16><<<spmm16_blocks, 256>>>();
    k_dense<64, 32, 2><<<dense_blocks, 128>>>(Wg1, bg1, Wb1, bb1);
    // layer 2: 32 -> 16
    k_spmm<8><<<spmm8_blocks, 256>>>();
    k_dense<32, 16, 3><<<dense_blocks, 128>>>(Wg2, bg2, Wb2, bb2);

    // scoring
    k_score<<<(BATCH * 32 + 255) / 256, 256>>>(users, pos, neg, ue, ee, out);
    (void)in_sizes; (void)n_in; (void)out_size;
}